// round 10
// baseline (speedup 1.0000x reference)
#include <cuda_runtime.h>
#include <cstdint>

// Problem constants (fixed by the reference)
#define HH 1024
#define WW 1024
#define HWSZ (HH * WW)      // 1,048,576 cells
#define NF 64               // features
#define NP 100000           // pillars

// Per-cell winner, encoded as (pillar_index + 1); 0 == empty.
// BSS zero-init makes the very first call correct; the gather kernel resets
// each winner word to 0 right after consuming it (each word is read by
// exactly one block), so every graph replay starts all-empty.
__device__ __align__(16) int g_winner[HWSZ];

// coords is int32 on device (JAX x64-off materializes int64 as int32).
// Layout [NP, 3]: x = col 2, y = col 1. Last-writer-wins == max pillar idx.
__global__ __launch_bounds__(128) void scatter_winner_kernel(
        const int* __restrict__ coords) {
    int p = blockIdx.x * blockDim.x + threadIdx.x;
    if (p >= NP) return;
    int x = coords[3 * p + 2];
    int y = coords[3 * p + 1];
    if (x >= 0 && x < WW && y >= 0 && y < HH) {
        atomicMax(&g_winner[y * WW + x], p + 1);
    }
}

// Block = 256 threads = 16 cell-groups x 16 feature-chunks.
// Threads 0-15 load the block's 16 winner int4s once, broadcast via smem,
// and IMMEDIATELY reset them to zero (fused clear — each winner word is
// owned by exactly one block, so this is race-free and graph-replay safe).
// Per thread: <=4 predicated LDG.128 feat loads, register transpose,
// 4x STG.128 evict-first stores (keep feat rows L2-resident).
__global__ __launch_bounds__(256) void gather_out_kernel(
        const float* __restrict__ feat,
        float* __restrict__ out) {
    __shared__ int4 s_w[16];

    int tid = threadIdx.x;
    int grp = tid & 15;         // cell-group within block (0..15)
    int f4  = tid >> 4;         // feature chunk (0..15)
    int gbase = blockIdx.x * 16;          // first cell-group of this block
    int c0 = (gbase + grp) * 4;           // first cell of this thread's group

    if (tid < 16) {
        int4* wp = reinterpret_cast<int4*>(&g_winner[(gbase + tid) * 4]);
        int4 wv = *wp;
        s_w[tid] = wv;
        *wp = make_int4(0, 0, 0, 0);      // fused reset for next replay
    }
    __syncthreads();

    int4 w4 = s_w[grp];
    int w[4] = {w4.x, w4.y, w4.z, w4.w};

    float4 v[4];
    #pragma unroll
    for (int j = 0; j < 4; j++) {
        if (w[j] > 0) {
            v[j] = __ldg(reinterpret_cast<const float4*>(
                feat + (size_t)(w[j] - 1) * NF + f4 * 4));
        } else {
            v[j] = make_float4(0.f, 0.f, 0.f, 0.f);
        }
    }
    #pragma unroll
    for (int k = 0; k < 4; k++) {
        float4 o;
        o.x = reinterpret_cast<const float*>(&v[0])[k];
        o.y = reinterpret_cast<const float*>(&v[1])[k];
        o.z = reinterpret_cast<const float*>(&v[2])[k];
        o.w = reinterpret_cast<const float*>(&v[3])[k];
        __stcs(reinterpret_cast<float4*>(
            out + (size_t)(f4 * 4 + k) * HWSZ + c0), o);
    }
}

extern "C" void kernel_launch(void* const* d_in, const int* in_sizes, int n_in,
                              void* d_out, int out_size) {
    const float* pillar_features = (const float*)d_in[0]; // [NP, 64] f32
    const int*   coords          = (const int*)d_in[1];   // [NP, 3] i32
    float*       out             = (float*)d_out;         // [1,64,1024,1024] f32

    {
        int threads = 128;
        int blocks = (NP + threads - 1) / threads;
        scatter_winner_kernel<<<blocks, threads>>>(coords);
    }
    {
        // (HWSZ/4) cell-groups, 16 per block -> 16384 blocks of 256 threads.
        int blocks = (HWSZ / 4) / 16;
        gather_out_kernel<<<blocks, 256>>>(pillar_features, out);
    }
}

// round 11
// speedup vs baseline: 1.1259x; 1.1259x over previous
#include <cuda_runtime.h>
#include <cstdint>

// Problem constants (fixed by the reference)
#define HH 1024
#define WW 1024
#define HWSZ (HH * WW)      // 1,048,576 cells
#define NF 64               // features
#define NP 100000           // pillars

// Per-cell winner, encoded as (pillar_index + 1); 0 == empty.
// BSS zero-init makes the very first call correct; the gather kernel resets
// each winner word to 0 after the block barrier (each word is read by
// exactly one block), so every graph replay starts all-empty.
__device__ __align__(16) int g_winner[HWSZ];

// coords is int32 on device (JAX x64-off materializes int64 as int32).
// Layout [NP, 3]: x = col 2, y = col 1. Last-writer-wins == max pillar idx.
__global__ __launch_bounds__(128) void scatter_winner_kernel(
        const int* __restrict__ coords) {
    int p = blockIdx.x * blockDim.x + threadIdx.x;
    if (p >= NP) return;
    int x = coords[3 * p + 2];
    int y = coords[3 * p + 1];
    if (x >= 0 && x < WW && y >= 0 && y < HH) {
        atomicMax(&g_winner[y * WW + x], p + 1);
    }
}

// Block = 256 threads = 16 cell-groups x 16 feature-chunks.
// Threads 0-15 load the block's 16 winner int4s once and broadcast via smem.
// The reset-to-zero store is issued AFTER __syncthreads (BAR.SYNC drains
// pending stores, so a pre-barrier global store would add a store round-trip
// to every block's prologue — the R10 regression). Post-barrier it overlaps
// the feature loads / output stores. Race-free: each winner word is owned by
// exactly one block, and the next scatter is graph-ordered after gather.
__global__ __launch_bounds__(256) void gather_out_kernel(
        const float* __restrict__ feat,
        float* __restrict__ out) {
    __shared__ int4 s_w[16];

    int tid = threadIdx.x;
    int grp = tid & 15;         // cell-group within block (0..15)
    int f4  = tid >> 4;         // feature chunk (0..15)
    int gbase = blockIdx.x * 16;          // first cell-group of this block
    int c0 = (gbase + grp) * 4;           // first cell of this thread's group

    int4 wv;
    if (tid < 16) {
        wv = __ldg(reinterpret_cast<const int4*>(&g_winner[(gbase + tid) * 4]));
        s_w[tid] = wv;
    }
    __syncthreads();

    // Fused clear for the next graph replay — after the barrier so the store
    // latency overlaps the memory work below instead of gating the barrier.
    if (tid < 16) {
        *reinterpret_cast<int4*>(&g_winner[(gbase + tid) * 4]) =
            make_int4(0, 0, 0, 0);
    }

    int4 w4 = s_w[grp];
    int w[4] = {w4.x, w4.y, w4.z, w4.w};

    float4 v[4];
    #pragma unroll
    for (int j = 0; j < 4; j++) {
        if (w[j] > 0) {
            v[j] = __ldg(reinterpret_cast<const float4*>(
                feat + (size_t)(w[j] - 1) * NF + f4 * 4));
        } else {
            v[j] = make_float4(0.f, 0.f, 0.f, 0.f);
        }
    }
    #pragma unroll
    for (int k = 0; k < 4; k++) {
        float4 o;
        o.x = reinterpret_cast<const float*>(&v[0])[k];
        o.y = reinterpret_cast<const float*>(&v[1])[k];
        o.z = reinterpret_cast<const float*>(&v[2])[k];
        o.w = reinterpret_cast<const float*>(&v[3])[k];
        __stcs(reinterpret_cast<float4*>(
            out + (size_t)(f4 * 4 + k) * HWSZ + c0), o);
    }
}

extern "C" void kernel_launch(void* const* d_in, const int* in_sizes, int n_in,
                              void* d_out, int out_size) {
    const float* pillar_features = (const float*)d_in[0]; // [NP, 64] f32
    const int*   coords          = (const int*)d_in[1];   // [NP, 3] i32
    float*       out             = (float*)d_out;         // [1,64,1024,1024] f32

    {
        int threads = 128;
        int blocks = (NP + threads - 1) / threads;
        scatter_winner_kernel<<<blocks, threads>>>(coords);
    }
    {
        // (HWSZ/4) cell-groups, 16 per block -> 16384 blocks of 256 threads.
        int blocks = (HWSZ / 4) / 16;
        gather_out_kernel<<<blocks, 256>>>(pillar_features, out);
    }
}

// round 12
// speedup vs baseline: 1.1339x; 1.0072x over previous
#include <cuda_runtime.h>
#include <cstdint>

// Problem constants (fixed by the reference)
#define HH 1024
#define WW 1024
#define HWSZ (HH * WW)      // 1,048,576 cells
#define NF 64               // features
#define NP 100000           // pillars

// Per-cell winner, encoded as (pillar_index + 1); 0 == empty.
// BSS zero-init makes the very first call correct; the gather kernel resets
// each winner word to 0 after the block barrier (each word is read by
// exactly one block), so every graph replay starts all-empty.
__device__ __align__(16) int g_winner[HWSZ];

// coords is int32 on device (JAX x64-off materializes int64 as int32).
// Layout [NP, 3]: x = col 2, y = col 1. Last-writer-wins == max pillar idx.
__global__ __launch_bounds__(128) void scatter_winner_kernel(
        const int* __restrict__ coords) {
    int p = blockIdx.x * blockDim.x + threadIdx.x;
    if (p >= NP) return;
    int x = coords[3 * p + 2];
    int y = coords[3 * p + 1];
    if (x >= 0 && x < WW && y >= 0 && y < HH) {
        atomicMax(&g_winner[y * WW + x], p + 1);
    }
    // PDL: completion (implicit trigger at kernel end) releases the gather's
    // cudaGridDependencySynchronize().
}

// Block = 256 threads = 16 cell-groups x 16 feature-chunks.
// Launched with programmatic stream serialization (PDL): the grid is
// scheduled while scatter still runs; cudaGridDependencySynchronize() below
// gates the first winner read on scatter completion + visibility.
// Threads 0-15 load the block's 16 winner int4s once, broadcast via smem;
// the reset store is AFTER __syncthreads (BAR.SYNC drains pre-barrier global
// stores — the R10 regression). Per thread: <=4 predicated LDG.128 feat
// loads, register transpose, 4x STG.128 evict-first stores.
__global__ __launch_bounds__(256) void gather_out_kernel(
        const float* __restrict__ feat,
        float* __restrict__ out) {
    __shared__ int4 s_w[16];

    int tid = threadIdx.x;
    int grp = tid & 15;         // cell-group within block (0..15)
    int f4  = tid >> 4;         // feature chunk (0..15)
    int gbase = blockIdx.x * 16;          // first cell-group of this block
    int c0 = (gbase + grp) * 4;           // first cell of this thread's group

    // Wait for the scatter kernel's results to be visible (PDL edge).
    cudaGridDependencySynchronize();

    if (tid < 16) {
        s_w[tid] = __ldg(reinterpret_cast<const int4*>(
            &g_winner[(gbase + tid) * 4]));
    }
    __syncthreads();

    // Fused clear for the next graph replay — post-barrier so the store
    // latency overlaps the memory work below instead of gating the barrier.
    if (tid < 16) {
        *reinterpret_cast<int4*>(&g_winner[(gbase + tid) * 4]) =
            make_int4(0, 0, 0, 0);
    }

    int4 w4 = s_w[grp];
    int w[4] = {w4.x, w4.y, w4.z, w4.w};

    float4 v[4];
    #pragma unroll
    for (int j = 0; j < 4; j++) {
        if (w[j] > 0) {
            v[j] = __ldg(reinterpret_cast<const float4*>(
                feat + (size_t)(w[j] - 1) * NF + f4 * 4));
        } else {
            v[j] = make_float4(0.f, 0.f, 0.f, 0.f);
        }
    }
    #pragma unroll
    for (int k = 0; k < 4; k++) {
        float4 o;
        o.x = reinterpret_cast<const float*>(&v[0])[k];
        o.y = reinterpret_cast<const float*>(&v[1])[k];
        o.z = reinterpret_cast<const float*>(&v[2])[k];
        o.w = reinterpret_cast<const float*>(&v[3])[k];
        __stcs(reinterpret_cast<float4*>(
            out + (size_t)(f4 * 4 + k) * HWSZ + c0), o);
    }
}

extern "C" void kernel_launch(void* const* d_in, const int* in_sizes, int n_in,
                              void* d_out, int out_size) {
    const float* pillar_features = (const float*)d_in[0]; // [NP, 64] f32
    const int*   coords          = (const int*)d_in[1];   // [NP, 3] i32
    float*       out             = (float*)d_out;         // [1,64,1024,1024] f32

    {
        int threads = 128;
        int blocks = (NP + threads - 1) / threads;
        scatter_winner_kernel<<<blocks, threads>>>(coords);
    }
    {
        // (HWSZ/4) cell-groups, 16 per block -> 16384 blocks of 256 threads.
        int blocks = (HWSZ / 4) / 16;

        cudaLaunchConfig_t cfg = {};
        cfg.gridDim = dim3((unsigned)blocks, 1, 1);
        cfg.blockDim = dim3(256, 1, 1);
        cfg.dynamicSmemBytes = 0;
        cfg.stream = 0;
        cudaLaunchAttribute attr;
        attr.id = cudaLaunchAttributeProgrammaticStreamSerialization;
        attr.val.programmaticStreamSerializationAllowed = 1;
        cfg.attrs = &attr;
        cfg.numAttrs = 1;

        cudaError_t e = cudaLaunchKernelEx(&cfg, gather_out_kernel,
                                           pillar_features, out);
        if (e != cudaSuccess) {
            // PDL unavailable in this capture context: plain launch fallback.
            // (cudaGridDependencySynchronize is a no-op without the PDL edge.)
            gather_out_kernel<<<blocks, 256>>>(pillar_features, out);
        }
    }
}